// round 2
// baseline (speedup 1.0000x reference)
#include <cuda_runtime.h>
#include <math.h>

// ---------------- static config ----------------
#define B_     8
#define C_     192
#define H_     128
#define W_     128
#define WS_    8
#define SHIFT_ 4
#define HEADS_ 4
#define HD_    48
#define L_     64
#define NW_    256                 // windows per image (16x16)
#define T_     (B_*NW_*L_)         // 131072 tokens
#define HID_   768

// ---------------- scratch (static device globals; no runtime allocation) ----
// Kernels reference these symbols directly — no cudaGetSymbolAddress needed.
__device__ float g_xw [(size_t)T_ * C_];    // windowed shifted input (shortcut)
__device__ float g_xn [(size_t)T_ * C_];    // ln1 out -> attn out -> x2
__device__ float g_x1 [(size_t)T_ * C_];    // residual-1 output
__device__ float g_big[(size_t)T_ * HID_];  // qkv (576 cols) then mlp hidden (768)

// ---------------- gather: x(B,C,H,W) --roll(-4,-4)+window--> g_xw[T][C] -----
__global__ __launch_bounds__(256) void gather_kernel(const float* __restrict__ x) {
    __shared__ float s[48 * 65];
    int blk = blockIdx.x;            // b*NW + n
    int b = blk / NW_;
    int n = blk % NW_;
    int wh = n >> 4, ww = n & 15;
    long tokbase = (long)blk * L_;
    int tid = threadIdx.x;
    for (int ci = 0; ci < 4; ci++) {          // 4 chunks of 48 channels
        #pragma unroll
        for (int t = 0; t < 12; t++) {
            int idx = tid + t * 256;          // 0..3071
            int c = idx >> 6, l = idx & 63;
            int hr = (wh * 8 + (l >> 3) + SHIFT_) & 127;
            int wc = (ww * 8 + (l & 7) + SHIFT_) & 127;
            s[c * 65 + l] = x[(((b * C_ + ci * 48 + c) * H_ + hr) << 7) + wc];
        }
        __syncthreads();
        #pragma unroll
        for (int t = 0; t < 12; t++) {
            int idx = tid + t * 256;
            int l = idx / 48, c = idx % 48;
            g_xw[(tokbase + l) * C_ + ci * 48 + c] = s[c * 65 + l];
        }
        __syncthreads();
    }
}

// ---------------- scatter: g_xn[T][C] --reverse window + roll(+4,+4)--> out -
__global__ __launch_bounds__(256) void scatter_kernel(float* __restrict__ out) {
    __shared__ float s[48 * 65];
    int blk = blockIdx.x;
    int b = blk / NW_;
    int n = blk % NW_;
    int wh = n >> 4, ww = n & 15;
    long tokbase = (long)blk * L_;
    int tid = threadIdx.x;
    for (int ci = 0; ci < 4; ci++) {
        #pragma unroll
        for (int t = 0; t < 12; t++) {
            int idx = tid + t * 256;
            int l = idx / 48, c = idx % 48;
            s[c * 65 + l] = g_xn[(tokbase + l) * C_ + ci * 48 + c];
        }
        __syncthreads();
        #pragma unroll
        for (int t = 0; t < 12; t++) {
            int idx = tid + t * 256;
            int c = idx >> 6, l = idx & 63;
            int hr = (wh * 8 + (l >> 3) + SHIFT_) & 127;
            int wc = (ww * 8 + (l & 7) + SHIFT_) & 127;
            out[(((b * C_ + ci * 48 + c) * H_ + hr) << 7) + wc] = s[c * 65 + l];
        }
        __syncthreads();
    }
}

// ---------------- layernorm: warp per token over C=192 ----------------------
__global__ __launch_bounds__(256) void ln_kernel(const float* __restrict__ in,
                                                 float* __restrict__ out,
                                                 const float* __restrict__ gam,
                                                 const float* __restrict__ bet) {
    int warp = threadIdx.x >> 5;
    int lane = threadIdx.x & 31;
    long tok = (long)blockIdx.x * 8 + warp;
    const float* row = in + tok * C_;
    float v[6];
    float sum = 0.f;
    #pragma unroll
    for (int u = 0; u < 6; u++) { v[u] = row[lane + 32 * u]; sum += v[u]; }
    #pragma unroll
    for (int o = 16; o; o >>= 1) sum += __shfl_xor_sync(0xffffffffu, sum, o);
    float mu = sum * (1.0f / 192.0f);
    float sq = 0.f;
    #pragma unroll
    for (int u = 0; u < 6; u++) { float d = v[u] - mu; sq += d * d; }
    #pragma unroll
    for (int o = 16; o; o >>= 1) sq += __shfl_xor_sync(0xffffffffu, sq, o);
    float rstd = rsqrtf(sq * (1.0f / 192.0f) + 1e-5f);
    float* orow = out + tok * C_;
    #pragma unroll
    for (int u = 0; u < 6; u++) {
        int c = lane + 32 * u;
        orow[c] = (v[u] - mu) * rstd * gam[c] + bet[c];
    }
}

// ---------------- SGEMM: O[M,N] = A[M,K] @ W[K,N] + bias (+gelu / +residual)
enum { OP_BIAS = 0, OP_BIAS_RES = 1, OP_BIAS_GELU = 2 };

template<int OP>
__global__ __launch_bounds__(256) void sgemm_kernel(const float* __restrict__ A,
                                                    const float* __restrict__ Wm,
                                                    const float* __restrict__ bias,
                                                    const float* __restrict__ R,
                                                    float* __restrict__ O,
                                                    int M, int N, int K) {
    __shared__ float As[16][132];   // [k][m], padded
    __shared__ float Bs[16][64];    // [k][n]
    int tid = threadIdx.x;
    int tx = tid & 15;              // n-dir (x4)
    int ty = tid >> 4;              // m-dir (x8)
    int m0 = blockIdx.y * 128;
    int n0 = blockIdx.x * 64;
    float acc[8][4] = {};
    for (int k0 = 0; k0 < K; k0 += 16) {
        #pragma unroll
        for (int i = 0; i < 2; i++) {
            int idx = tid + i * 256;              // 0..511 float4s
            int row = idx >> 2, kq = idx & 3;
            float4 v = *(const float4*)(A + (long)(m0 + row) * K + k0 + kq * 4);
            As[kq * 4 + 0][row] = v.x;
            As[kq * 4 + 1][row] = v.y;
            As[kq * 4 + 2][row] = v.z;
            As[kq * 4 + 3][row] = v.w;
        }
        {
            int row = tid >> 4, cq = tid & 15;
            *(float4*)&Bs[row][cq * 4] =
                *(const float4*)(Wm + (long)(k0 + row) * N + n0 + cq * 4);
        }
        __syncthreads();
        #pragma unroll
        for (int kk = 0; kk < 16; kk++) {
            float a[8], bb[4];
            #pragma unroll
            for (int i = 0; i < 8; i++) a[i] = As[kk][ty * 8 + i];
            #pragma unroll
            for (int j = 0; j < 4; j++) bb[j] = Bs[kk][tx * 4 + j];
            #pragma unroll
            for (int i = 0; i < 8; i++)
                #pragma unroll
                for (int j = 0; j < 4; j++) acc[i][j] += a[i] * bb[j];
        }
        __syncthreads();
    }
    #pragma unroll
    for (int i = 0; i < 8; i++) {
        long row = m0 + ty * 8 + i;
        #pragma unroll
        for (int j = 0; j < 4; j++) {
            int col = n0 + tx * 4 + j;
            float v = acc[i][j] + bias[col];
            if (OP == OP_BIAS_GELU) v = 0.5f * v * (1.0f + erff(v * 0.70710678118654752f));
            if (OP == OP_BIAS_RES)  v += R[row * N + col];
            O[row * N + col] = v;
        }
    }
}

// ---------------- windowed attention: one block per (b, window, head) -------
__global__ __launch_bounds__(256) void attn_kernel(const float* __restrict__ bias_table) {
    __shared__ float sq[64 * 49];
    __shared__ float sk[64 * 49];   // reused for V in phase 2
    __shared__ float ss[64 * 65];   // attention probabilities
    int blk = blockIdx.x;            // (b*NW + n)*HEADS + head
    int head = blk & 3;
    int bn = blk >> 2;
    int n = bn % NW_;
    int wh = n >> 4, ww = n & 15;
    long tokbase = (long)bn * 64;
    int tid = threadIdx.x;

    // load Q, K (64 x 48 each) from g_big (qkv layout: [T][576])
    #pragma unroll
    for (int t = 0; t < 12; t++) {
        int idx = tid + t * 256;
        int l = idx / 48, d = idx % 48;
        const float* base = g_big + (tokbase + l) * 576 + head * 48 + d;
        sq[l * 49 + d] = base[0];
        sk[l * 49 + d] = base[192];
    }
    __syncthreads();

    int r = tid >> 2;                // row 0..63
    int part = tid & 3;              // 16-col chunk
    int j0 = part * 16;

    // scores for 16 columns of row r
    float sv[16];
    #pragma unroll
    for (int u = 0; u < 16; u++) sv[u] = 0.f;
    #pragma unroll
    for (int d = 0; d < 48; d++) {
        float qv = sq[r * 49 + d];
        #pragma unroll
        for (int u = 0; u < 16; u++) sv[u] += qv * sk[(j0 + u) * 49 + d];
    }

    // bias + shift mask (region-id based; regions only mixed when wh==15 / ww==15)
    int ih = r >> 3, iw = r & 7;
    int reg_i = ((wh == 15) ? (ih < 4 ? 3 : 6) : 0) + ((ww == 15) ? (iw < 4 ? 1 : 2) : 0);
    const float scale = 0.14433756729740643f;   // 1/sqrt(48)
    const float* bt = bias_table + head * 225;
    #pragma unroll
    for (int u = 0; u < 16; u++) {
        int j = j0 + u;
        int jh = j >> 3, jw = j & 7;
        int reg_j = ((wh == 15) ? (jh < 4 ? 3 : 6) : 0) + ((ww == 15) ? (jw < 4 ? 1 : 2) : 0);
        float bv = (reg_i != reg_j) ? -100.0f : bt[(ih - jh + 7) * 15 + (iw - jw + 7)];
        sv[u] = sv[u] * scale + bv;
    }

    // softmax across 4 lanes holding row r (lanes r*4..r*4+3 in same warp)
    float mx = sv[0];
    #pragma unroll
    for (int u = 1; u < 16; u++) mx = fmaxf(mx, sv[u]);
    mx = fmaxf(mx, __shfl_xor_sync(0xffffffffu, mx, 1));
    mx = fmaxf(mx, __shfl_xor_sync(0xffffffffu, mx, 2));
    float sum = 0.f;
    #pragma unroll
    for (int u = 0; u < 16; u++) { sv[u] = __expf(sv[u] - mx); sum += sv[u]; }
    sum += __shfl_xor_sync(0xffffffffu, sum, 1);
    sum += __shfl_xor_sync(0xffffffffu, sum, 2);
    float inv = 1.0f / sum;
    #pragma unroll
    for (int u = 0; u < 16; u++) ss[r * 65 + j0 + u] = sv[u] * inv;
    __syncthreads();        // all score work done; safe to overwrite sk with V

    // load V into sk
    #pragma unroll
    for (int t = 0; t < 12; t++) {
        int idx = tid + t * 256;
        int l = idx / 48, d = idx % 48;
        sk[l * 49 + d] = g_big[(tokbase + l) * 576 + 384 + head * 48 + d];
    }
    __syncthreads();

    // out[r][d0..d0+11] = attn_row_r . V   (written into g_xn)
    float o[12];
    #pragma unroll
    for (int dd = 0; dd < 12; dd++) o[dd] = 0.f;
    int d0 = part * 12;
    #pragma unroll 4
    for (int j = 0; j < 64; j++) {
        float a = ss[r * 65 + j];
        #pragma unroll
        for (int dd = 0; dd < 12; dd++) o[dd] += a * sk[j * 49 + d0 + dd];
    }
    float* op = g_xn + (tokbase + r) * C_ + head * 48 + d0;
    #pragma unroll
    for (int dd = 0; dd < 12; dd++) op[dd] = o[dd];
}

// ---------------- helper kernels to get symbol addresses without host APIs --
// All data-flow wiring is done by referencing the globals inside kernels.
// For the SGEMM (which takes pointers), we use tiny launcher-visible device
// pointer fetch: a kernel writes symbol addresses into a pinned-free pattern is
// NOT allowed, so instead we specialize wrappers that pass the symbol directly.

__global__ __launch_bounds__(256) void ln1_wrap(const float* g, const float* b) {
    // never launched; placeholder (kept minimal)
}

// ---------------- launcher ---------------------------------------------------
// SGEMM needs raw pointers; device symbols decay to valid device pointers when
// referenced in device code, but from host we cannot take their address without
// an API call. Solution: wrap each GEMM invocation in a thin __global__ that
// would add overhead — instead, simpler: small trampoline kernels below bind
// the symbols. To keep one SGEMM body, we pass an enum selecting src/dst.

enum Buf { BUF_XW = 0, BUF_XN = 1, BUF_X1 = 2, BUF_BIG = 3, BUF_EXT = 4 };

__device__ __forceinline__ float* buf_ptr(int sel, float* ext) {
    switch (sel) {
        case BUF_XW:  return g_xw;
        case BUF_XN:  return g_xn;
        case BUF_X1:  return g_x1;
        case BUF_BIG: return g_big;
        default:      return ext;
    }
}

template<int OP>
__global__ __launch_bounds__(256) void sgemm_sym(int selA, int selR, int selO,
                                                 const float* __restrict__ Wm,
                                                 const float* __restrict__ bias,
                                                 int M, int N, int K) {
    const float* A = buf_ptr(selA, nullptr);
    const float* R = buf_ptr(selR, nullptr);
    float* O = buf_ptr(selO, nullptr);
    // ---- same body as sgemm_kernel ----
    __shared__ float As[16][132];
    __shared__ float Bs[16][64];
    int tid = threadIdx.x;
    int tx = tid & 15;
    int ty = tid >> 4;
    int m0 = blockIdx.y * 128;
    int n0 = blockIdx.x * 64;
    float acc[8][4] = {};
    for (int k0 = 0; k0 < K; k0 += 16) {
        #pragma unroll
        for (int i = 0; i < 2; i++) {
            int idx = tid + i * 256;
            int row = idx >> 2, kq = idx & 3;
            float4 v = *(const float4*)(A + (long)(m0 + row) * K + k0 + kq * 4);
            As[kq * 4 + 0][row] = v.x;
            As[kq * 4 + 1][row] = v.y;
            As[kq * 4 + 2][row] = v.z;
            As[kq * 4 + 3][row] = v.w;
        }
        {
            int row = tid >> 4, cq = tid & 15;
            *(float4*)&Bs[row][cq * 4] =
                *(const float4*)(Wm + (long)(k0 + row) * N + n0 + cq * 4);
        }
        __syncthreads();
        #pragma unroll
        for (int kk = 0; kk < 16; kk++) {
            float a[8], bb[4];
            #pragma unroll
            for (int i = 0; i < 8; i++) a[i] = As[kk][ty * 8 + i];
            #pragma unroll
            for (int j = 0; j < 4; j++) bb[j] = Bs[kk][tx * 4 + j];
            #pragma unroll
            for (int i = 0; i < 8; i++)
                #pragma unroll
                for (int j = 0; j < 4; j++) acc[i][j] += a[i] * bb[j];
        }
        __syncthreads();
    }
    #pragma unroll
    for (int i = 0; i < 8; i++) {
        long row = m0 + ty * 8 + i;
        #pragma unroll
        for (int j = 0; j < 4; j++) {
            int col = n0 + tx * 4 + j;
            float v = acc[i][j] + bias[col];
            if (OP == OP_BIAS_GELU) v = 0.5f * v * (1.0f + erff(v * 0.70710678118654752f));
            if (OP == OP_BIAS_RES)  v += R[row * N + col];
            O[row * N + col] = v;
        }
    }
}

__global__ __launch_bounds__(256) void ln_sym(int selI, int selO,
                                              const float* __restrict__ gam,
                                              const float* __restrict__ bet) {
    const float* in = buf_ptr(selI, nullptr);
    float* out = buf_ptr(selO, nullptr);
    int warp = threadIdx.x >> 5;
    int lane = threadIdx.x & 31;
    long tok = (long)blockIdx.x * 8 + warp;
    const float* row = in + tok * C_;
    float v[6];
    float sum = 0.f;
    #pragma unroll
    for (int u = 0; u < 6; u++) { v[u] = row[lane + 32 * u]; sum += v[u]; }
    #pragma unroll
    for (int o = 16; o; o >>= 1) sum += __shfl_xor_sync(0xffffffffu, sum, o);
    float mu = sum * (1.0f / 192.0f);
    float sq = 0.f;
    #pragma unroll
    for (int u = 0; u < 6; u++) { float d = v[u] - mu; sq += d * d; }
    #pragma unroll
    for (int o = 16; o; o >>= 1) sq += __shfl_xor_sync(0xffffffffu, sq, o);
    float rstd = rsqrtf(sq * (1.0f / 192.0f) + 1e-5f);
    float* orow = out + tok * C_;
    #pragma unroll
    for (int u = 0; u < 6; u++) {
        int c = lane + 32 * u;
        orow[c] = (v[u] - mu) * rstd * gam[c] + bet[c];
    }
}

extern "C" void kernel_launch(void* const* d_in, const int* in_sizes, int n_in,
                              void* d_out, int out_size) {
    const float* x   = (const float*)d_in[0];
    const float* bt  = (const float*)d_in[1];
    const float* qw  = (const float*)d_in[2];
    const float* qb  = (const float*)d_in[3];
    const float* pw  = (const float*)d_in[4];
    const float* pb  = (const float*)d_in[5];
    const float* g1  = (const float*)d_in[6];
    const float* b1  = (const float*)d_in[7];
    const float* g2  = (const float*)d_in[8];
    const float* b2  = (const float*)d_in[9];
    const float* w1  = (const float*)d_in[10];
    const float* bb1 = (const float*)d_in[11];
    const float* w2  = (const float*)d_in[12];
    const float* bb2 = (const float*)d_in[13];
    float* out = (float*)d_out;

    // 1. shifted window partition  (x -> g_xw)
    gather_kernel<<<B_ * NW_, 256>>>(x);
    // 2. LN1 (g_xw -> g_xn)
    ln_sym<<<T_ / 8, 256>>>(BUF_XW, BUF_XN, g1, b1);
    // 3. QKV GEMM: [T,192] @ [192,576]  (g_xn -> g_big)
    sgemm_sym<OP_BIAS><<<dim3(576 / 64, T_ / 128), 256>>>(BUF_XN, BUF_XN, BUF_BIG, qw, qb, T_, 576, 192);
    // 4. windowed attention (g_big -> g_xn, head-major C)
    attn_kernel<<<B_ * NW_ * HEADS_, 256>>>(bt);
    // 5. proj GEMM + residual (g_xn @ pw + g_xw -> g_x1)
    sgemm_sym<OP_BIAS_RES><<<dim3(192 / 64, T_ / 128), 256>>>(BUF_XN, BUF_XW, BUF_X1, pw, pb, T_, 192, 192);
    // 6. LN2 (g_x1 -> g_xw)
    ln_sym<<<T_ / 8, 256>>>(BUF_X1, BUF_XW, g2, b2);
    // 7. MLP1 + exact GELU: [T,192] @ [192,768]  (g_xw -> g_big)
    sgemm_sym<OP_BIAS_GELU><<<dim3(768 / 64, T_ / 128), 256>>>(BUF_XW, BUF_XW, BUF_BIG, w1, bb1, T_, 768, 192);
    // 8. MLP2 + residual: [T,768] @ [768,192] + g_x1 -> g_xn
    sgemm_sym<OP_BIAS_RES><<<dim3(192 / 64, T_ / 128), 256>>>(BUF_BIG, BUF_X1, BUF_XN, w2, bb2, T_, 192, 768);
    // 9. window reverse + roll(+4,+4)  (g_xn -> out)
    scatter_kernel<<<B_ * NW_, 256>>>(out);
}

// round 3
// speedup vs baseline: 1.4637x; 1.4637x over previous
#include <cuda_runtime.h>
#include <math.h>
#include <stdint.h>

// ---------------- static config ----------------
#define B_     8
#define C_     192
#define H_     128
#define W_     128
#define WS_    8
#define SHIFT_ 4
#define HEADS_ 4
#define HD_    48
#define L_     64
#define NW_    256                 // windows per image (16x16)
#define T_     (B_*NW_*L_)         // 131072 tokens
#define HID_   768

// ---------------- scratch (static device globals; no runtime allocation) ----
__device__ float g_xw [(size_t)T_ * C_];    // windowed shifted input (shortcut)
__device__ float g_xn [(size_t)T_ * C_];    // ln1 out -> attn out -> x2
__device__ float g_x1 [(size_t)T_ * C_];    // residual-1 output
__device__ float g_big[(size_t)T_ * HID_];  // qkv (576 cols) then mlp hidden (768)

enum Buf { BUF_XW = 0, BUF_XN = 1, BUF_X1 = 2, BUF_BIG = 3 };

__device__ __forceinline__ float* buf_ptr(int sel) {
    switch (sel) {
        case BUF_XW:  return g_xw;
        case BUF_XN:  return g_xn;
        case BUF_X1:  return g_x1;
        default:      return g_big;
    }
}

// ---------------- gather: x(B,C,H,W) --roll(-4,-4)+window--> g_xw[T][C] -----
__global__ __launch_bounds__(256) void gather_kernel(const float* __restrict__ x) {
    __shared__ float s[48 * 65];
    int blk = blockIdx.x;            // b*NW + n
    int b = blk / NW_;
    int n = blk % NW_;
    int wh = n >> 4, ww = n & 15;
    long tokbase = (long)blk * L_;
    int tid = threadIdx.x;
    for (int ci = 0; ci < 4; ci++) {          // 4 chunks of 48 channels
        #pragma unroll
        for (int t = 0; t < 12; t++) {
            int idx = tid + t * 256;          // 0..3071
            int c = idx >> 6, l = idx & 63;
            int hr = (wh * 8 + (l >> 3) + SHIFT_) & 127;
            int wc = (ww * 8 + (l & 7) + SHIFT_) & 127;
            s[c * 65 + l] = x[(((b * C_ + ci * 48 + c) * H_ + hr) << 7) + wc];
        }
        __syncthreads();
        #pragma unroll
        for (int t = 0; t < 12; t++) {
            int idx = tid + t * 256;
            int l = idx / 48, c = idx % 48;
            g_xw[(tokbase + l) * C_ + ci * 48 + c] = s[c * 65 + l];
        }
        __syncthreads();
    }
}

// ---------------- scatter: g_xn[T][C] --reverse window + roll(+4,+4)--> out -
__global__ __launch_bounds__(256) void scatter_kernel(float* __restrict__ out) {
    __shared__ float s[48 * 65];
    int blk = blockIdx.x;
    int b = blk / NW_;
    int n = blk % NW_;
    int wh = n >> 4, ww = n & 15;
    long tokbase = (long)blk * L_;
    int tid = threadIdx.x;
    for (int ci = 0; ci < 4; ci++) {
        #pragma unroll
        for (int t = 0; t < 12; t++) {
            int idx = tid + t * 256;
            int l = idx / 48, c = idx % 48;
            s[c * 65 + l] = g_xn[(tokbase + l) * C_ + ci * 48 + c];
        }
        __syncthreads();
        #pragma unroll
        for (int t = 0; t < 12; t++) {
            int idx = tid + t * 256;
            int c = idx >> 6, l = idx & 63;
            int hr = (wh * 8 + (l >> 3) + SHIFT_) & 127;
            int wc = (ww * 8 + (l & 7) + SHIFT_) & 127;
            out[(((b * C_ + ci * 48 + c) * H_ + hr) << 7) + wc] = s[c * 65 + l];
        }
        __syncthreads();
    }
}

// ---------------- layernorm: warp per token over C=192 ----------------------
__global__ __launch_bounds__(256) void ln_sym(int selI, int selO,
                                              const float* __restrict__ gam,
                                              const float* __restrict__ bet) {
    const float* in = buf_ptr(selI);
    float* out = buf_ptr(selO);
    int warp = threadIdx.x >> 5;
    int lane = threadIdx.x & 31;
    long tok = (long)blockIdx.x * 8 + warp;
    const float* row = in + tok * C_;
    float v[6];
    float sum = 0.f;
    #pragma unroll
    for (int u = 0; u < 6; u++) { v[u] = row[lane + 32 * u]; sum += v[u]; }
    #pragma unroll
    for (int o = 16; o; o >>= 1) sum += __shfl_xor_sync(0xffffffffu, sum, o);
    float mu = sum * (1.0f / 192.0f);
    float sq = 0.f;
    #pragma unroll
    for (int u = 0; u < 6; u++) { float d = v[u] - mu; sq += d * d; }
    #pragma unroll
    for (int o = 16; o; o >>= 1) sq += __shfl_xor_sync(0xffffffffu, sq, o);
    float rstd = rsqrtf(sq * (1.0f / 192.0f) + 1e-5f);
    float* orow = out + tok * C_;
    #pragma unroll
    for (int u = 0; u < 6; u++) {
        int c = lane + 32 * u;
        orow[c] = (v[u] - mu) * rstd * gam[c] + bet[c];
    }
}

// ---------------- TF32 tensor-core GEMM -------------------------------------
// O[M,N] = A[M,K] @ W[K,N] + bias (+gelu / +residual)
// 128x64 block tile, 8 warps (4m x 2n), 32x32 per warp, mma.m16n8k8.tf32
enum { OP_BIAS = 0, OP_BIAS_RES = 1, OP_BIAS_GELU = 2 };

__device__ __forceinline__ uint32_t to_tf32(float f) {
    uint32_t r;
    asm("cvt.rna.tf32.f32 %0, %1;" : "=r"(r) : "f"(f));
    return r;
}

__device__ __forceinline__ void mma_tf32(float c[4],
                                         const uint32_t a[4], const uint32_t b[2]) {
    asm volatile(
        "mma.sync.aligned.m16n8k8.row.col.f32.tf32.tf32.f32 "
        "{%0,%1,%2,%3}, {%4,%5,%6,%7}, {%8,%9}, {%0,%1,%2,%3};"
        : "+f"(c[0]), "+f"(c[1]), "+f"(c[2]), "+f"(c[3])
        : "r"(a[0]), "r"(a[1]), "r"(a[2]), "r"(a[3]), "r"(b[0]), "r"(b[1]));
}

template<int OP>
__global__ __launch_bounds__(256) void tgemm_sym(int selA, int selR, int selO,
                                                 const float* __restrict__ Wm,
                                                 const float* __restrict__ bias,
                                                 int M, int N, int K) {
    const float* A = buf_ptr(selA);
    const float* R = buf_ptr(selR);
    float* O = buf_ptr(selO);

    __shared__ uint32_t As[16][132];   // [k][m], tf32 bits, padded (+4)
    __shared__ uint32_t Bs[16][68];    // [k][n], tf32 bits, padded (+4)

    int tid = threadIdx.x;
    int warp = tid >> 5;
    int lane = tid & 31;
    int gid = lane >> 2;               // 0..7
    int tig = lane & 3;                // 0..3
    int wm = (warp >> 1) * 32;         // 0,32,64,96
    int wn = (warp & 1) * 32;          // 0,32
    int m0 = blockIdx.y * 128;
    int n0 = blockIdx.x * 64;

    float acc[2][4][4];
    #pragma unroll
    for (int i = 0; i < 2; i++)
        #pragma unroll
        for (int j = 0; j < 4; j++)
            #pragma unroll
            for (int c = 0; c < 4; c++) acc[i][j][c] = 0.f;

    for (int k0 = 0; k0 < K; k0 += 16) {
        // load A tile: 128 rows x 16 k
        #pragma unroll
        for (int i = 0; i < 2; i++) {
            int idx = tid + i * 256;              // 0..511 float4s
            int row = idx >> 2, kq = idx & 3;
            float4 v = *(const float4*)(A + (long)(m0 + row) * K + k0 + kq * 4);
            As[kq * 4 + 0][row] = to_tf32(v.x);
            As[kq * 4 + 1][row] = to_tf32(v.y);
            As[kq * 4 + 2][row] = to_tf32(v.z);
            As[kq * 4 + 3][row] = to_tf32(v.w);
        }
        // load B tile: 16 k rows x 64 n
        {
            int row = tid >> 4, cq = tid & 15;
            float4 v = *(const float4*)(Wm + (long)(k0 + row) * N + n0 + cq * 4);
            Bs[row][cq * 4 + 0] = to_tf32(v.x);
            Bs[row][cq * 4 + 1] = to_tf32(v.y);
            Bs[row][cq * 4 + 2] = to_tf32(v.z);
            Bs[row][cq * 4 + 3] = to_tf32(v.w);
        }
        __syncthreads();

        #pragma unroll
        for (int ks = 0; ks < 2; ks++) {
            int kb = ks * 8;
            uint32_t a[2][4], b[4][2];
            #pragma unroll
            for (int mi = 0; mi < 2; mi++) {
                int mrow = wm + mi * 16 + gid;
                a[mi][0] = As[kb + tig][mrow];
                a[mi][1] = As[kb + tig][mrow + 8];
                a[mi][2] = As[kb + tig + 4][mrow];
                a[mi][3] = As[kb + tig + 4][mrow + 8];
            }
            #pragma unroll
            for (int ni = 0; ni < 4; ni++) {
                int ncol = wn + ni * 8 + gid;
                b[ni][0] = Bs[kb + tig][ncol];
                b[ni][1] = Bs[kb + tig + 4][ncol];
            }
            #pragma unroll
            for (int mi = 0; mi < 2; mi++)
                #pragma unroll
                for (int ni = 0; ni < 4; ni++)
                    mma_tf32(acc[mi][ni], a[mi], b[ni]);
        }
        __syncthreads();
    }

    // epilogue: c0,c1 -> (row, col..col+1); c2,c3 -> (row+8, col..col+1)
    #pragma unroll
    for (int mi = 0; mi < 2; mi++) {
        #pragma unroll
        for (int ni = 0; ni < 4; ni++) {
            int col = n0 + wn + ni * 8 + tig * 2;
            float bv0 = bias[col], bv1 = bias[col + 1];
            #pragma unroll
            for (int h = 0; h < 2; h++) {
                long row = m0 + wm + mi * 16 + gid + h * 8;
                float v0 = acc[mi][ni][h * 2 + 0] + bv0;
                float v1 = acc[mi][ni][h * 2 + 1] + bv1;
                if (OP == OP_BIAS_GELU) {
                    v0 = 0.5f * v0 * (1.0f + erff(v0 * 0.70710678118654752f));
                    v1 = 0.5f * v1 * (1.0f + erff(v1 * 0.70710678118654752f));
                }
                if (OP == OP_BIAS_RES) {
                    v0 += R[row * N + col];
                    v1 += R[row * N + col + 1];
                }
                float2 o = make_float2(v0, v1);
                *(float2*)(O + row * N + col) = o;
            }
        }
    }
}

// ---------------- windowed attention: one block per (b, window, head) -------
__global__ __launch_bounds__(256) void attn_kernel(const float* __restrict__ bias_table) {
    __shared__ float sq[64 * 49];
    __shared__ float sk[64 * 49];   // reused for V in phase 2
    __shared__ float ss[64 * 65];   // attention probabilities
    int blk = blockIdx.x;            // (b*NW + n)*HEADS + head
    int head = blk & 3;
    int bn = blk >> 2;
    int n = bn % NW_;
    int wh = n >> 4, ww = n & 15;
    long tokbase = (long)bn * 64;
    int tid = threadIdx.x;

    // load Q, K (64 x 48 each) from g_big (qkv layout: [T][576])
    #pragma unroll
    for (int t = 0; t < 12; t++) {
        int idx = tid + t * 256;
        int l = idx / 48, d = idx % 48;
        const float* base = g_big + (tokbase + l) * 576 + head * 48 + d;
        sq[l * 49 + d] = base[0];
        sk[l * 49 + d] = base[192];
    }
    __syncthreads();

    int r = tid >> 2;                // row 0..63
    int part = tid & 3;              // 16-col chunk
    int j0 = part * 16;

    float sv[16];
    #pragma unroll
    for (int u = 0; u < 16; u++) sv[u] = 0.f;
    #pragma unroll
    for (int d = 0; d < 48; d++) {
        float qv = sq[r * 49 + d];
        #pragma unroll
        for (int u = 0; u < 16; u++) sv[u] += qv * sk[(j0 + u) * 49 + d];
    }

    int ih = r >> 3, iw = r & 7;
    int reg_i = ((wh == 15) ? (ih < 4 ? 3 : 6) : 0) + ((ww == 15) ? (iw < 4 ? 1 : 2) : 0);
    const float scale = 0.14433756729740643f;   // 1/sqrt(48)
    const float* bt = bias_table + head * 225;
    #pragma unroll
    for (int u = 0; u < 16; u++) {
        int j = j0 + u;
        int jh = j >> 3, jw = j & 7;
        int reg_j = ((wh == 15) ? (jh < 4 ? 3 : 6) : 0) + ((ww == 15) ? (jw < 4 ? 1 : 2) : 0);
        float bv = (reg_i != reg_j) ? -100.0f : bt[(ih - jh + 7) * 15 + (iw - jw + 7)];
        sv[u] = sv[u] * scale + bv;
    }

    float mx = sv[0];
    #pragma unroll
    for (int u = 1; u < 16; u++) mx = fmaxf(mx, sv[u]);
    mx = fmaxf(mx, __shfl_xor_sync(0xffffffffu, mx, 1));
    mx = fmaxf(mx, __shfl_xor_sync(0xffffffffu, mx, 2));
    float sum = 0.f;
    #pragma unroll
    for (int u = 0; u < 16; u++) { sv[u] = __expf(sv[u] - mx); sum += sv[u]; }
    sum += __shfl_xor_sync(0xffffffffu, sum, 1);
    sum += __shfl_xor_sync(0xffffffffu, sum, 2);
    float inv = 1.0f / sum;
    #pragma unroll
    for (int u = 0; u < 16; u++) ss[r * 65 + j0 + u] = sv[u] * inv;
    __syncthreads();

    #pragma unroll
    for (int t = 0; t < 12; t++) {
        int idx = tid + t * 256;
        int l = idx / 48, d = idx % 48;
        sk[l * 49 + d] = g_big[(tokbase + l) * 576 + 384 + head * 48 + d];
    }
    __syncthreads();

    float o[12];
    #pragma unroll
    for (int dd = 0; dd < 12; dd++) o[dd] = 0.f;
    int d0 = part * 12;
    #pragma unroll 4
    for (int j = 0; j < 64; j++) {
        float a = ss[r * 65 + j];
        #pragma unroll
        for (int dd = 0; dd < 12; dd++) o[dd] += a * sk[j * 49 + d0 + dd];
    }
    float* op = g_xn + (tokbase + r) * C_ + head * 48 + d0;
    #pragma unroll
    for (int dd = 0; dd < 12; dd++) op[dd] = o[dd];
}

// ---------------- launcher ---------------------------------------------------
extern "C" void kernel_launch(void* const* d_in, const int* in_sizes, int n_in,
                              void* d_out, int out_size) {
    const float* x   = (const float*)d_in[0];
    const float* bt  = (const float*)d_in[1];
    const float* qw  = (const float*)d_in[2];
    const float* qb  = (const float*)d_in[3];
    const float* pw  = (const float*)d_in[4];
    const float* pb  = (const float*)d_in[5];
    const float* g1  = (const float*)d_in[6];
    const float* b1  = (const float*)d_in[7];
    const float* g2  = (const float*)d_in[8];
    const float* b2  = (const float*)d_in[9];
    const float* w1  = (const float*)d_in[10];
    const float* bb1 = (const float*)d_in[11];
    const float* w2  = (const float*)d_in[12];
    const float* bb2 = (const float*)d_in[13];
    float* out = (float*)d_out;

    // 1. shifted window partition  (x -> g_xw)
    gather_kernel<<<B_ * NW_, 256>>>(x);
    // 2. LN1 (g_xw -> g_xn)
    ln_sym<<<T_ / 8, 256>>>(BUF_XW, BUF_XN, g1, b1);
    // 3. QKV GEMM: [T,192] @ [192,576]  (g_xn -> g_big)
    tgemm_sym<OP_BIAS><<<dim3(576 / 64, T_ / 128), 256>>>(BUF_XN, BUF_XN, BUF_BIG, qw, qb, T_, 576, 192);
    // 4. windowed attention (g_big -> g_xn, head-major C)
    attn_kernel<<<B_ * NW_ * HEADS_, 256>>>(bt);
    // 5. proj GEMM + residual (g_xn @ pw + g_xw -> g_x1)
    tgemm_sym<OP_BIAS_RES><<<dim3(192 / 64, T_ / 128), 256>>>(BUF_XN, BUF_XW, BUF_X1, pw, pb, T_, 192, 192);
    // 6. LN2 (g_x1 -> g_xw)
    ln_sym<<<T_ / 8, 256>>>(BUF_X1, BUF_XW, g2, b2);
    // 7. MLP1 + exact GELU: [T,192] @ [192,768]  (g_xw -> g_big)
    tgemm_sym<OP_BIAS_GELU><<<dim3(768 / 64, T_ / 128), 256>>>(BUF_XW, BUF_XW, BUF_BIG, w1, bb1, T_, 768, 192);
    // 8. MLP2 + residual: [T,768] @ [768,192] + g_x1 -> g_xn
    tgemm_sym<OP_BIAS_RES><<<dim3(192 / 64, T_ / 128), 256>>>(BUF_BIG, BUF_X1, BUF_XN, w2, bb2, T_, 192, 768);
    // 9. window reverse + roll(+4,+4)  (g_xn -> out)
    scatter_kernel<<<B_ * NW_, 256>>>(out);
}

// round 4
// speedup vs baseline: 1.9892x; 1.3590x over previous
#include <cuda_runtime.h>
#include <math.h>
#include <stdint.h>

// ---------------- static config ----------------
#define B_     8
#define C_     192
#define H_     128
#define W_     128
#define WS_    8
#define SHIFT_ 4
#define HEADS_ 4
#define HD_    48
#define L_     64
#define NW_    256                 // windows per image (16x16)
#define T_     (B_*NW_*L_)         // 131072 tokens
#define HID_   768

// ---------------- scratch (static device globals; no runtime allocation) ----
__device__ float g_xw [(size_t)T_ * C_];    // windowed shifted input (shortcut)
__device__ float g_xn [(size_t)T_ * C_];    // ln1 out -> attn out -> x2
__device__ float g_x1 [(size_t)T_ * C_];    // residual-1 output
__device__ float g_big[(size_t)T_ * HID_];  // qkv (576 cols) then mlp hidden (768)

enum Buf { BUF_XW = 0, BUF_XN = 1, BUF_X1 = 2, BUF_BIG = 3 };

__device__ __forceinline__ float* buf_ptr(int sel) {
    switch (sel) {
        case BUF_XW:  return g_xw;
        case BUF_XN:  return g_xn;
        case BUF_X1:  return g_x1;
        default:      return g_big;
    }
}

__device__ __forceinline__ uint32_t to_tf32(float f) {
    uint32_t r;
    asm("cvt.rna.tf32.f32 %0, %1;" : "=r"(r) : "f"(f));
    return r;
}

__device__ __forceinline__ void mma_tf32(float c[4],
                                         const uint32_t a[4], const uint32_t b[2]) {
    asm volatile(
        "mma.sync.aligned.m16n8k8.row.col.f32.tf32.tf32.f32 "
        "{%0,%1,%2,%3}, {%4,%5,%6,%7}, {%8,%9}, {%0,%1,%2,%3};"
        : "+f"(c[0]), "+f"(c[1]), "+f"(c[2]), "+f"(c[3])
        : "r"(a[0]), "r"(a[1]), "r"(a[2]), "r"(a[3]), "r"(b[0]), "r"(b[1]));
}

// ---------------- gather: x(B,C,H,W) --roll(-4,-4)+window--> g_xw[T][C] -----
__global__ __launch_bounds__(256) void gather_kernel(const float* __restrict__ x) {
    __shared__ float s[48 * 65];
    int blk = blockIdx.x;            // b*NW + n
    int b = blk / NW_;
    int n = blk % NW_;
    int wh = n >> 4, ww = n & 15;
    long tokbase = (long)blk * L_;
    int tid = threadIdx.x;
    for (int ci = 0; ci < 4; ci++) {          // 4 chunks of 48 channels
        #pragma unroll
        for (int t = 0; t < 12; t++) {
            int idx = tid + t * 256;          // 0..3071
            int c = idx >> 6, l = idx & 63;
            int hr = (wh * 8 + (l >> 3) + SHIFT_) & 127;
            int wc = (ww * 8 + (l & 7) + SHIFT_) & 127;
            s[c * 65 + l] = x[(((b * C_ + ci * 48 + c) * H_ + hr) << 7) + wc];
        }
        __syncthreads();
        #pragma unroll
        for (int t = 0; t < 12; t++) {
            int idx = tid + t * 256;
            int l = idx / 48, c = idx % 48;
            g_xw[(tokbase + l) * C_ + ci * 48 + c] = s[c * 65 + l];
        }
        __syncthreads();
    }
}

// ---------------- scatter: g_xn[T][C] --reverse window + roll(+4,+4)--> out -
__global__ __launch_bounds__(256) void scatter_kernel(float* __restrict__ out) {
    __shared__ float s[48 * 65];
    int blk = blockIdx.x;
    int b = blk / NW_;
    int n = blk % NW_;
    int wh = n >> 4, ww = n & 15;
    long tokbase = (long)blk * L_;
    int tid = threadIdx.x;
    for (int ci = 0; ci < 4; ci++) {
        #pragma unroll
        for (int t = 0; t < 12; t++) {
            int idx = tid + t * 256;
            int l = idx / 48, c = idx % 48;
            s[c * 65 + l] = g_xn[(tokbase + l) * C_ + ci * 48 + c];
        }
        __syncthreads();
        #pragma unroll
        for (int t = 0; t < 12; t++) {
            int idx = tid + t * 256;
            int c = idx >> 6, l = idx & 63;
            int hr = (wh * 8 + (l >> 3) + SHIFT_) & 127;
            int wc = (ww * 8 + (l & 7) + SHIFT_) & 127;
            out[(((b * C_ + ci * 48 + c) * H_ + hr) << 7) + wc] = s[c * 65 + l];
        }
        __syncthreads();
    }
}

// ---------------- layernorm: warp per token over C=192 ----------------------
__global__ __launch_bounds__(256) void ln_sym(int selI, int selO,
                                              const float* __restrict__ gam,
                                              const float* __restrict__ bet) {
    const float* in = buf_ptr(selI);
    float* out = buf_ptr(selO);
    int warp = threadIdx.x >> 5;
    int lane = threadIdx.x & 31;
    long tok = (long)blockIdx.x * 8 + warp;
    const float* row = in + tok * C_;
    float v[6];
    float sum = 0.f;
    #pragma unroll
    for (int u = 0; u < 6; u++) { v[u] = row[lane + 32 * u]; sum += v[u]; }
    #pragma unroll
    for (int o = 16; o; o >>= 1) sum += __shfl_xor_sync(0xffffffffu, sum, o);
    float mu = sum * (1.0f / 192.0f);
    float sq = 0.f;
    #pragma unroll
    for (int u = 0; u < 6; u++) { float d = v[u] - mu; sq += d * d; }
    #pragma unroll
    for (int o = 16; o; o >>= 1) sq += __shfl_xor_sync(0xffffffffu, sq, o);
    float rstd = rsqrtf(sq * (1.0f / 192.0f) + 1e-5f);
    float* orow = out + tok * C_;
    #pragma unroll
    for (int u = 0; u < 6; u++) {
        int c = lane + 32 * u;
        orow[c] = (v[u] - mu) * rstd * gam[c] + bet[c];
    }
}

// ---------------- TF32 tensor-core GEMM -------------------------------------
enum { OP_BIAS = 0, OP_BIAS_RES = 1, OP_BIAS_GELU = 2 };

template<int OP>
__global__ __launch_bounds__(256) void tgemm_sym(int selA, int selR, int selO,
                                                 const float* __restrict__ Wm,
                                                 const float* __restrict__ bias,
                                                 int M, int N, int K) {
    const float* A = buf_ptr(selA);
    const float* R = buf_ptr(selR);
    float* O = buf_ptr(selO);

    __shared__ uint32_t As[16][136];   // [k][m], stride 136 ≡ 8 mod 32 (conflict-free)
    __shared__ uint32_t Bs[16][72];    // [k][n], stride 72  ≡ 8 mod 32

    int tid = threadIdx.x;
    int warp = tid >> 5;
    int lane = tid & 31;
    int gid = lane >> 2;               // 0..7
    int tig = lane & 3;                // 0..3
    int wm = (warp >> 1) * 32;         // 0,32,64,96
    int wn = (warp & 1) * 32;          // 0,32
    int m0 = blockIdx.y * 128;
    int n0 = blockIdx.x * 64;

    float acc[2][4][4];
    #pragma unroll
    for (int i = 0; i < 2; i++)
        #pragma unroll
        for (int j = 0; j < 4; j++)
            #pragma unroll
            for (int c = 0; c < 4; c++) acc[i][j][c] = 0.f;

    for (int k0 = 0; k0 < K; k0 += 16) {
        #pragma unroll
        for (int i = 0; i < 2; i++) {
            int idx = tid + i * 256;              // 0..511 float4s
            int row = idx >> 2, kq = idx & 3;
            float4 v = *(const float4*)(A + (long)(m0 + row) * K + k0 + kq * 4);
            As[kq * 4 + 0][row] = to_tf32(v.x);
            As[kq * 4 + 1][row] = to_tf32(v.y);
            As[kq * 4 + 2][row] = to_tf32(v.z);
            As[kq * 4 + 3][row] = to_tf32(v.w);
        }
        {
            int row = tid >> 4, cq = tid & 15;
            float4 v = *(const float4*)(Wm + (long)(k0 + row) * N + n0 + cq * 4);
            Bs[row][cq * 4 + 0] = to_tf32(v.x);
            Bs[row][cq * 4 + 1] = to_tf32(v.y);
            Bs[row][cq * 4 + 2] = to_tf32(v.z);
            Bs[row][cq * 4 + 3] = to_tf32(v.w);
        }
        __syncthreads();

        #pragma unroll
        for (int ks = 0; ks < 2; ks++) {
            int kb = ks * 8;
            uint32_t a[2][4], b[4][2];
            #pragma unroll
            for (int mi = 0; mi < 2; mi++) {
                int mrow = wm + mi * 16 + gid;
                a[mi][0] = As[kb + tig][mrow];
                a[mi][1] = As[kb + tig][mrow + 8];
                a[mi][2] = As[kb + tig + 4][mrow];
                a[mi][3] = As[kb + tig + 4][mrow + 8];
            }
            #pragma unroll
            for (int ni = 0; ni < 4; ni++) {
                int ncol = wn + ni * 8 + gid;
                b[ni][0] = Bs[kb + tig][ncol];
                b[ni][1] = Bs[kb + tig + 4][ncol];
            }
            #pragma unroll
            for (int mi = 0; mi < 2; mi++)
                #pragma unroll
                for (int ni = 0; ni < 4; ni++)
                    mma_tf32(acc[mi][ni], a[mi], b[ni]);
        }
        __syncthreads();
    }

    #pragma unroll
    for (int mi = 0; mi < 2; mi++) {
        #pragma unroll
        for (int ni = 0; ni < 4; ni++) {
            int col = n0 + wn + ni * 8 + tig * 2;
            float bv0 = bias[col], bv1 = bias[col + 1];
            #pragma unroll
            for (int h = 0; h < 2; h++) {
                long row = m0 + wm + mi * 16 + gid + h * 8;
                float v0 = acc[mi][ni][h * 2 + 0] + bv0;
                float v1 = acc[mi][ni][h * 2 + 1] + bv1;
                if (OP == OP_BIAS_GELU) {
                    v0 = 0.5f * v0 * (1.0f + erff(v0 * 0.70710678118654752f));
                    v1 = 0.5f * v1 * (1.0f + erff(v1 * 0.70710678118654752f));
                }
                if (OP == OP_BIAS_RES) {
                    v0 += R[row * N + col];
                    v1 += R[row * N + col + 1];
                }
                float2 o = make_float2(v0, v1);
                *(float2*)(O + row * N + col) = o;
            }
        }
    }
}

// ---------------- tensor-core windowed attention ----------------------------
// one 128-thread block per (b, window, head); 4 warps, 16 rows each
#define QK_STR 72   // ≡ 8 mod 32 -> conflict-free B/A fragment loads
#define V_STR  56   // ≡ 24 mod 32 -> conflict-free
#define P_STR  68   // ≡ 4 mod 32 -> conflict-free A fragment loads

__global__ __launch_bounds__(128) void attn_mma_kernel(const float* __restrict__ bias_table) {
    __shared__ uint32_t sQK[2 * 48 * QK_STR];   // Q at 0, K at 3456; reused as P (needs 64*68=4352)
    __shared__ uint32_t sV[64 * V_STR];
    __shared__ float bb[225];

    uint32_t* sQ = sQK;
    uint32_t* sK = sQK + 48 * QK_STR;
    uint32_t* sP = sQK;

    int blk = blockIdx.x;            // (b*NW + n)*HEADS + head
    int head = blk & 3;
    int bn = blk >> 2;
    int n = bn % NW_;
    int wh = n >> 4, ww = n & 15;
    long tokbase = (long)bn * 64;
    int tid = threadIdx.x;
    int warp = tid >> 5;
    int lane = tid & 31;
    int gid = lane >> 2;             // 0..7
    int tig = lane & 3;              // 0..3

    // bias table slice for this head
    for (int t = tid; t < 225; t += 128) bb[t] = bias_table[head * 225 + t];

    // load Q (scaled, transposed), K (transposed), V (row-major), all tf32
    const float scale = 0.14433756729740643f;   // 1/sqrt(48)
    for (int t = tid; t < 768; t += 128) {       // 64 rows x 12 float4
        int l = t / 12, q4 = t % 12, d = q4 * 4;
        const float* base = g_big + (tokbase + l) * 576 + head * 48 + d;
        float4 q = *(const float4*)(base);
        float4 k = *(const float4*)(base + 192);
        float4 v = *(const float4*)(base + 384);
        sQ[(d + 0) * QK_STR + l] = to_tf32(q.x * scale);
        sQ[(d + 1) * QK_STR + l] = to_tf32(q.y * scale);
        sQ[(d + 2) * QK_STR + l] = to_tf32(q.z * scale);
        sQ[(d + 3) * QK_STR + l] = to_tf32(q.w * scale);
        sK[(d + 0) * QK_STR + l] = to_tf32(k.x);
        sK[(d + 1) * QK_STR + l] = to_tf32(k.y);
        sK[(d + 2) * QK_STR + l] = to_tf32(k.z);
        sK[(d + 3) * QK_STR + l] = to_tf32(k.w);
        uint4 vv = make_uint4(to_tf32(v.x), to_tf32(v.y), to_tf32(v.z), to_tf32(v.w));
        *(uint4*)&sV[l * V_STR + d] = vv;
    }
    __syncthreads();

    // phase 1: scores S = (Q*scale) K^T  (64x64, K=48) -> acc
    int r0 = warp * 16 + gid;        // rows r0, r0+8 owned by this lane
    float acc[8][4];
    #pragma unroll
    for (int ni = 0; ni < 8; ni++)
        #pragma unroll
        for (int c = 0; c < 4; c++) acc[ni][c] = 0.f;

    #pragma unroll
    for (int kb = 0; kb < 6; kb++) {
        int k = kb * 8;
        uint32_t a[4];
        a[0] = sQ[(k + tig) * QK_STR + r0];
        a[1] = sQ[(k + tig) * QK_STR + r0 + 8];
        a[2] = sQ[(k + tig + 4) * QK_STR + r0];
        a[3] = sQ[(k + tig + 4) * QK_STR + r0 + 8];
        #pragma unroll
        for (int ni = 0; ni < 8; ni++) {
            uint32_t b[2];
            b[0] = sK[(k + tig) * QK_STR + ni * 8 + gid];
            b[1] = sK[(k + tig + 4) * QK_STR + ni * 8 + gid];
            mma_tf32(acc[ni], a, b);
        }
    }

    // phase 2: bias + shift mask + softmax (rows r0 and r0+8)
    int ih0 = r0 >> 3, iw0 = r0 & 7;
    int r1 = r0 + 8;
    int ih1 = r1 >> 3, iw1 = r1 & 7;
    int reg_i0 = ((wh == 15) ? (ih0 < 4 ? 3 : 6) : 0) + ((ww == 15) ? (iw0 < 4 ? 1 : 2) : 0);
    int reg_i1 = ((wh == 15) ? (ih1 < 4 ? 3 : 6) : 0) + ((ww == 15) ? (iw1 < 4 ? 1 : 2) : 0);

    float mx0 = -1e30f, mx1 = -1e30f;
    #pragma unroll
    for (int ni = 0; ni < 8; ni++) {
        #pragma unroll
        for (int hh = 0; hh < 2; hh++) {
            int j = ni * 8 + tig * 2 + hh;
            int jh = j >> 3, jw = j & 7;
            int reg_j = ((wh == 15) ? (jh < 4 ? 3 : 6) : 0) + ((ww == 15) ? (jw < 4 ? 1 : 2) : 0);
            float bt0 = (reg_i0 != reg_j) ? -100.0f : bb[(ih0 - jh + 7) * 15 + (iw0 - jw + 7)];
            float bt1 = (reg_i1 != reg_j) ? -100.0f : bb[(ih1 - jh + 7) * 15 + (iw1 - jw + 7)];
            acc[ni][hh]     += bt0;
            acc[ni][2 + hh] += bt1;
            mx0 = fmaxf(mx0, acc[ni][hh]);
            mx1 = fmaxf(mx1, acc[ni][2 + hh]);
        }
    }
    mx0 = fmaxf(mx0, __shfl_xor_sync(0xffffffffu, mx0, 1));
    mx0 = fmaxf(mx0, __shfl_xor_sync(0xffffffffu, mx0, 2));
    mx1 = fmaxf(mx1, __shfl_xor_sync(0xffffffffu, mx1, 1));
    mx1 = fmaxf(mx1, __shfl_xor_sync(0xffffffffu, mx1, 2));
    float s0 = 0.f, s1 = 0.f;
    #pragma unroll
    for (int ni = 0; ni < 8; ni++) {
        #pragma unroll
        for (int hh = 0; hh < 2; hh++) {
            acc[ni][hh]     = __expf(acc[ni][hh] - mx0);     s0 += acc[ni][hh];
            acc[ni][2 + hh] = __expf(acc[ni][2 + hh] - mx1); s1 += acc[ni][2 + hh];
        }
    }
    s0 += __shfl_xor_sync(0xffffffffu, s0, 1);
    s0 += __shfl_xor_sync(0xffffffffu, s0, 2);
    s1 += __shfl_xor_sync(0xffffffffu, s1, 1);
    s1 += __shfl_xor_sync(0xffffffffu, s1, 2);
    float inv0 = 1.0f / s0, inv1 = 1.0f / s1;

    __syncthreads();   // all warps done reading sQ/sK before P overwrites them

    #pragma unroll
    for (int ni = 0; ni < 8; ni++) {
        int j = ni * 8 + tig * 2;
        sP[r0 * P_STR + j]     = to_tf32(acc[ni][0] * inv0);
        sP[r0 * P_STR + j + 1] = to_tf32(acc[ni][1] * inv0);
        sP[r1 * P_STR + j]     = to_tf32(acc[ni][2] * inv1);
        sP[r1 * P_STR + j + 1] = to_tf32(acc[ni][3] * inv1);
    }
    __syncthreads();

    // phase 3: O = P V  (64x48, K=64)
    float oacc[6][4];
    #pragma unroll
    for (int ni = 0; ni < 6; ni++)
        #pragma unroll
        for (int c = 0; c < 4; c++) oacc[ni][c] = 0.f;

    #pragma unroll
    for (int kt = 0; kt < 8; kt++) {
        int k = kt * 8;
        uint32_t a[4];
        a[0] = sP[r0 * P_STR + k + tig];
        a[1] = sP[r1 * P_STR + k + tig];
        a[2] = sP[r0 * P_STR + k + tig + 4];
        a[3] = sP[r1 * P_STR + k + tig + 4];
        #pragma unroll
        for (int ni = 0; ni < 6; ni++) {
            uint32_t b[2];
            b[0] = sV[(k + tig) * V_STR + ni * 8 + gid];
            b[1] = sV[(k + tig + 4) * V_STR + ni * 8 + gid];
            mma_tf32(oacc[ni], a, b);
        }
    }

    // write O into g_xn (head-major within C)
    #pragma unroll
    for (int ni = 0; ni < 6; ni++) {
        int col = ni * 8 + tig * 2;
        float* p0 = g_xn + (tokbase + r0) * C_ + head * 48 + col;
        float* p1 = g_xn + (tokbase + r1) * C_ + head * 48 + col;
        *(float2*)p0 = make_float2(oacc[ni][0], oacc[ni][1]);
        *(float2*)p1 = make_float2(oacc[ni][2], oacc[ni][3]);
    }
}

// ---------------- launcher ---------------------------------------------------
extern "C" void kernel_launch(void* const* d_in, const int* in_sizes, int n_in,
                              void* d_out, int out_size) {
    const float* x   = (const float*)d_in[0];
    const float* bt  = (const float*)d_in[1];
    const float* qw  = (const float*)d_in[2];
    const float* qb  = (const float*)d_in[3];
    const float* pw  = (const float*)d_in[4];
    const float* pb  = (const float*)d_in[5];
    const float* g1  = (const float*)d_in[6];
    const float* b1  = (const float*)d_in[7];
    const float* g2  = (const float*)d_in[8];
    const float* b2  = (const float*)d_in[9];
    const float* w1  = (const float*)d_in[10];
    const float* bb1 = (const float*)d_in[11];
    const float* w2  = (const float*)d_in[12];
    const float* bb2 = (const float*)d_in[13];
    float* out = (float*)d_out;

    // 1. shifted window partition  (x -> g_xw)
    gather_kernel<<<B_ * NW_, 256>>>(x);
    // 2. LN1 (g_xw -> g_xn)
    ln_sym<<<T_ / 8, 256>>>(BUF_XW, BUF_XN, g1, b1);
    // 3. QKV GEMM: [T,192] @ [192,576]  (g_xn -> g_big)
    tgemm_sym<OP_BIAS><<<dim3(576 / 64, T_ / 128), 256>>>(BUF_XN, BUF_XN, BUF_BIG, qw, qb, T_, 576, 192);
    // 4. tensor-core windowed attention (g_big -> g_xn, head-major C)
    attn_mma_kernel<<<B_ * NW_ * HEADS_, 128>>>(bt);
    // 5. proj GEMM + residual (g_xn @ pw + g_xw -> g_x1)
    tgemm_sym<OP_BIAS_RES><<<dim3(192 / 64, T_ / 128), 256>>>(BUF_XN, BUF_XW, BUF_X1, pw, pb, T_, 192, 192);
    // 6. LN2 (g_x1 -> g_xw)
    ln_sym<<<T_ / 8, 256>>>(BUF_X1, BUF_XW, g2, b2);
    // 7. MLP1 + exact GELU: [T,192] @ [192,768]  (g_xw -> g_big)
    tgemm_sym<OP_BIAS_GELU><<<dim3(768 / 64, T_ / 128), 256>>>(BUF_XW, BUF_XW, BUF_BIG, w1, bb1, T_, 768, 192);
    // 8. MLP2 + residual: [T,768] @ [768,192] + g_x1 -> g_xn
    tgemm_sym<OP_BIAS_RES><<<dim3(192 / 64, T_ / 128), 256>>>(BUF_BIG, BUF_X1, BUF_XN, w2, bb2, T_, 192, 768);
    // 9. window reverse + roll(+4,+4)  (g_xn -> out)
    scatter_kernel<<<B_ * NW_, 256>>>(out);
}